// round 1
// baseline (speedup 1.0000x reference)
#include <cuda_runtime.h>
#include <cstdint>

#define Bb 2
#define Ss 4096
#define HIDN 2048
#define Hh 16
#define HKVn 8
#define Dd 128
#define Mm 256
#define NCn 32
#define CHn 128

// ---------------- scratch (static device allocations are allowed) -------------
__device__ float g_q[(size_t)Bb * Hh * Ss * Dd];        // (b,h,s,d) post-rope
__device__ float g_k[(size_t)Bb * HKVn * Ss * Dd];      // (b,kvh,s,d) post-rope
__device__ float g_v[(size_t)Bb * HKVn * Ss * Dd];      // (b,kvh,s,d)
__device__ float g_phiq[(size_t)Bb * Hh * Ss * Mm];     // (b,h,s,m)
__device__ float g_phik[(size_t)Bb * HKVn * Ss * Mm];   // (b,kvh,s,m)  (z then phi)
__device__ float g_kv[(size_t)Bb * HKVn * NCn * Mm * Dd]; // per-chunk KV, then excl prefix
__device__ float g_ksum[(size_t)Bb * HKVn * NCn * Mm];  // per-chunk k colsum, then excl prefix
__device__ float g_attn[(size_t)Bb * Ss * Hh * Dd];     // (b,s,h*D+d)
__device__ float g_part[4096];
__device__ float g_zmax;

// ---------------- generic tiled GEMM: C[r,c] = sum_k A[r,k] * W[c,k] ----------
// mode 0: C row-major (r*N + c).  mode 1: head-split transpose to (b,h,s,d).
__global__ void gemm_tn(const float* __restrict__ A, const float* __restrict__ W,
                        float* __restrict__ C, int Mr, int Nc, int K,
                        int mode, int NH)
{
    __shared__ float As[64][17];
    __shared__ float Wsm[64][17];
    int t = threadIdx.x;
    int tx = t & 15, ty = t >> 4;
    int row0 = blockIdx.y * 64, col0 = blockIdx.x * 64;
    const float* Ap = A + (size_t)row0 * K;
    const float* Wp = W + (size_t)col0 * K;
    float acc[4][4];
#pragma unroll
    for (int i = 0; i < 4; i++)
#pragma unroll
        for (int j = 0; j < 4; j++) acc[i][j] = 0.f;

    for (int k0 = 0; k0 < K; k0 += 16) {
#pragma unroll
        for (int i = 0; i < 4; i++) {
            int idx = t + i * 256;
            int r = idx >> 4, c = idx & 15;
            As[r][c]  = Ap[(size_t)r * K + k0 + c];
            Wsm[r][c] = Wp[(size_t)r * K + k0 + c];
        }
        __syncthreads();
#pragma unroll
        for (int kk = 0; kk < 16; kk++) {
            float a[4], w[4];
#pragma unroll
            for (int i = 0; i < 4; i++) a[i] = As[ty * 4 + i][kk];
#pragma unroll
            for (int j = 0; j < 4; j++) w[j] = Wsm[tx * 4 + j][kk];
#pragma unroll
            for (int i = 0; i < 4; i++)
#pragma unroll
                for (int j = 0; j < 4; j++) acc[i][j] = fmaf(a[i], w[j], acc[i][j]);
        }
        __syncthreads();
    }
#pragma unroll
    for (int i = 0; i < 4; i++) {
        int r = row0 + ty * 4 + i;
#pragma unroll
        for (int j = 0; j < 4; j++) {
            int c = col0 + tx * 4 + j;
            if (mode == 0) {
                C[(size_t)r * Nc + c] = acc[i][j];
            } else {
                int b = r / Ss, s = r % Ss;
                int h = c >> 7, d = c & 127;
                C[((((size_t)b * NH + h) * Ss + s) << 7) + d] = acc[i][j];
            }
        }
    }
}

// ---------------- RoPE in-place on (b,h,s,d) ---------------------------------
__global__ void rope_kernel(float* __restrict__ X, const float* __restrict__ cosp,
                            const float* __restrict__ sinp, int NH)
{
    size_t idx = (size_t)blockIdx.x * blockDim.x + threadIdx.x;
    int d = idx & 63;
    size_t r = idx >> 6;
    int s = (int)(r % Ss); r /= Ss;
    int h = (int)(r % NH); int b = (int)(r / NH);
    size_t base = (((size_t)b * NH + h) * Ss + s) << 7;
    float x1 = X[base + d], x2 = X[base + d + 64];
    size_t cb = (((size_t)b * Ss + s) << 7);
    float c1 = cosp[cb + d],      s1 = sinp[cb + d];
    float c2 = cosp[cb + d + 64], s2 = sinp[cb + d + 64];
    X[base + d]      = fmaf(x1, c1, -x2 * s1);
    X[base + d + 64] = fmaf(x2, c2,  x1 * s2);
}

// ---------------- feature map: 64 rows/block, full M=256 ---------------------
// isq=1: phi = exp(z - rowmax)*M^-0.5 + eps.  isq=0: store raw z + block max.
__global__ void featmap_kernel(const float* __restrict__ X, const float* __restrict__ proj,
                               float* __restrict__ out, float* __restrict__ partials, int isq)
{
    extern __shared__ float sm[];
    float* Ps = sm;               // 256*129
    float* Xs = sm + 256 * 129;   // 64*129
    int t = threadIdx.x;
    int tx = t & 15, ty = t >> 4;
    size_t row0 = (size_t)blockIdx.x * 64;

    for (int i = t; i < 256 * 128; i += 256) {
        int m = i >> 7, d = i & 127;
        Ps[m * 129 + d] = proj[i];
    }
    const float sc = 0.29730177875068026f;  // 128^(-1/4)
    for (int i = t; i < 64 * 128; i += 256) {
        int r = i >> 7, d = i & 127;
        Xs[r * 129 + d] = X[(row0 + r) * 128 + d] * sc;
    }
    __syncthreads();

    float acc[4][16];
#pragma unroll
    for (int i = 0; i < 4; i++)
#pragma unroll
        for (int j = 0; j < 16; j++) acc[i][j] = 0.f;
    float sq[4] = {0.f, 0.f, 0.f, 0.f};

    for (int d = 0; d < 128; d++) {
        float a[4];
#pragma unroll
        for (int i = 0; i < 4; i++) {
            a[i] = Xs[(ty * 4 + i) * 129 + d];
            sq[i] = fmaf(a[i], a[i], sq[i]);
        }
#pragma unroll
        for (int j = 0; j < 16; j++) {
            float p = Ps[(tx + 16 * j) * 129 + d];
#pragma unroll
            for (int i = 0; i < 4; i++) acc[i][j] = fmaf(a[i], p, acc[i][j]);
        }
    }
    float rmax[4];
#pragma unroll
    for (int i = 0; i < 4; i++) {
        float hlf = 0.5f * sq[i];
        float mx = -1e30f;
#pragma unroll
        for (int j = 0; j < 16; j++) {
            acc[i][j] -= hlf;
            mx = fmaxf(mx, acc[i][j]);
        }
        rmax[i] = mx;
    }
    if (isq) {
#pragma unroll
        for (int o = 1; o < 16; o <<= 1)
#pragma unroll
            for (int i = 0; i < 4; i++)
                rmax[i] = fmaxf(rmax[i], __shfl_xor_sync(0xffffffffu, rmax[i], o));
#pragma unroll
        for (int i = 0; i < 4; i++) {
            size_t ro = (row0 + ty * 4 + i) * 256;
#pragma unroll
            for (int j = 0; j < 16; j++)
                out[ro + tx + 16 * j] = expf(acc[i][j] - rmax[i]) * 0.0625f + 1e-6f;
        }
    } else {
#pragma unroll
        for (int i = 0; i < 4; i++) {
            size_t ro = (row0 + ty * 4 + i) * 256;
#pragma unroll
            for (int j = 0; j < 16; j++)
                out[ro + tx + 16 * j] = acc[i][j];
        }
        __shared__ float red[256];
        float mx = fmaxf(fmaxf(rmax[0], rmax[1]), fmaxf(rmax[2], rmax[3]));
        red[t] = mx;
        __syncthreads();
        for (int o = 128; o > 0; o >>= 1) {
            if (t < o) red[t] = fmaxf(red[t], red[t + o]);
            __syncthreads();
        }
        if (t == 0) partials[blockIdx.x] = red[0];
    }
}

__global__ void reduce_max_kernel(const float* __restrict__ partials, int n)
{
    __shared__ float red[256];
    int t = threadIdx.x;
    float mx = -1e30f;
    for (int i = t; i < n; i += 256) mx = fmaxf(mx, partials[i]);
    red[t] = mx; __syncthreads();
    for (int o = 128; o > 0; o >>= 1) {
        if (t < o) red[t] = fmaxf(red[t], red[t + o]);
        __syncthreads();
    }
    if (t == 0) g_zmax = red[0];
}

__global__ void expk_kernel(float* __restrict__ Z, size_t n)
{
    size_t i = (size_t)blockIdx.x * blockDim.x + threadIdx.x;
    if (i < n) Z[i] = expf(Z[i] - g_zmax) * 0.0625f + 1e-6f;
}

// ---------------- per-chunk KV = phi_k^T @ v (M x D), d-half per block -------
__global__ void kvchunk_kernel()
{
    __shared__ float pks[32 * 256];
    __shared__ float vs[32 * 64];
    int dh = blockIdx.x;        // 0/1
    int c  = blockIdx.y;        // chunk
    int bh = blockIdx.z;        // b*HKV + kvh
    int t = threadIdx.x, tx = t & 15, ty = t >> 4;
    const float* pk = g_phik + ((size_t)bh * Ss + (size_t)c * 128) * 256;
    const float* vv = g_v    + ((size_t)bh * Ss + (size_t)c * 128) * 128 + dh * 64;
    float acc[16][4];
#pragma unroll
    for (int a = 0; a < 16; a++)
#pragma unroll
        for (int b2 = 0; b2 < 4; b2++) acc[a][b2] = 0.f;

    for (int j0 = 0; j0 < 128; j0 += 32) {
        __syncthreads();
        for (int i = t; i < 32 * 256; i += 256) pks[i] = pk[(size_t)j0 * 256 + i];
        for (int i = t; i < 32 * 64; i += 256) {
            int j = i >> 6, d = i & 63;
            vs[i] = vv[(size_t)(j0 + j) * 128 + d];
        }
        __syncthreads();
        for (int j = 0; j < 32; j++) {
            float a[16], b4[4];
#pragma unroll
            for (int mi = 0; mi < 16; mi++) a[mi] = pks[j * 256 + tx + 16 * mi];
#pragma unroll
            for (int di = 0; di < 4; di++) b4[di] = vs[j * 64 + ty * 4 + di];
#pragma unroll
            for (int mi = 0; mi < 16; mi++)
#pragma unroll
                for (int di = 0; di < 4; di++)
                    acc[mi][di] = fmaf(a[mi], b4[di], acc[mi][di]);
        }
    }
    float* outp = g_kv + (((size_t)bh * NCn + c) * 256) * 128 + dh * 64;
#pragma unroll
    for (int mi = 0; mi < 16; mi++)
#pragma unroll
        for (int di = 0; di < 4; di++)
            outp[(size_t)(tx + 16 * mi) * 128 + ty * 4 + di] = acc[mi][di];
}

// exclusive prefix over chunks, in place
__global__ void kvprefix_kernel()
{
    int e = blockIdx.x * 256 + threadIdx.x;   // 0..32767
    int bh = blockIdx.y;
    size_t base = (size_t)bh * NCn * 32768 + e;
    float run = 0.f;
    for (int c = 0; c < NCn; c++) {
        size_t p = base + (size_t)c * 32768;
        float v = g_kv[p];
        g_kv[p] = run;
        run += v;
    }
}

__global__ void ksum_kernel()
{
    int c = blockIdx.x, bh = blockIdx.y, m = threadIdx.x;
    const float* pk = g_phik + ((size_t)bh * Ss + (size_t)c * 128) * 256;
    float s = 0.f;
    for (int j = 0; j < 128; j++) s += pk[(size_t)j * 256 + m];
    g_ksum[((size_t)bh * NCn + c) * 256 + m] = s;
}

__global__ void ksumprefix_kernel()
{
    int bh = blockIdx.x, m = threadIdx.x;
    float run = 0.f;
    for (int c = 0; c < NCn; c++) {
        size_t p = ((size_t)bh * NCn + c) * 256 + m;
        float v = g_ksum[p];
        g_ksum[p] = run;
        run += v;
    }
}

// ---------------- attention main: one (b,h,chunk) per block ------------------
__global__ void attn_kernel()
{
    extern __shared__ float sm[];
    float* Psm   = sm;            // 128*129 = 16512
    float* buf   = sm + 16512;    // 16512
    float* den_s = sm + 33024;    // 128
    int t = threadIdx.x, tx = t & 15, ty = t >> 4;
    int c = blockIdx.x, h = blockIdx.y, b = blockIdx.z;
    int kvh = h >> 1;
    size_t qbase = (((size_t)(b * Hh + h)) * Ss + (size_t)c * 128) * 256;
    size_t kbase = (((size_t)(b * HKVn + kvh)) * Ss + (size_t)c * 128) * 256;
    size_t vbase = (((size_t)(b * HKVn + kvh)) * Ss + (size_t)c * 128) * 128;

    float* pq_s = buf;           // 128*33 = 4224
    float* pk_s = buf + 4224;    // 4224
    float* ksp  = buf + 8448;    // 256
    float* den2 = buf + 8704;    // 128

    if (t < 128) den2[t] = 0.f;
    if (t < 256) ksp[t] = g_ksum[(((size_t)(b * HKVn + kvh)) * NCn + c) * 256 + t];

    float accP[8][8];
#pragma unroll
    for (int i = 0; i < 8; i++)
#pragma unroll
        for (int j = 0; j < 8; j++) accP[i][j] = 0.f;

    // ----- P = phi_q @ phi_k^T  (+ den2 = phi_q . ksum_pre) -----
    for (int m0 = 0; m0 < 256; m0 += 32) {
        __syncthreads();
        for (int i = t; i < 128 * 32; i += 256) {
            int r = i >> 5, cc = i & 31;
            pq_s[r * 33 + cc] = g_phiq[qbase + (size_t)r * 256 + m0 + cc];
            pk_s[r * 33 + cc] = g_phik[kbase + (size_t)r * 256 + m0 + cc];
        }
        __syncthreads();
        for (int m = 0; m < 32; m++) {
            float a[8], w[8];
#pragma unroll
            for (int ii = 0; ii < 8; ii++) a[ii] = pq_s[(ty * 8 + ii) * 33 + m];
#pragma unroll
            for (int jj = 0; jj < 8; jj++) w[jj] = pk_s[(tx + 16 * jj) * 33 + m];
#pragma unroll
            for (int ii = 0; ii < 8; ii++)
#pragma unroll
                for (int jj = 0; jj < 8; jj++)
                    accP[ii][jj] = fmaf(a[ii], w[jj], accP[ii][jj]);
        }
        if (t < 128) {
            float s = 0.f;
            for (int m = 0; m < 32; m++) s = fmaf(pq_s[t * 33 + m], ksp[m0 + m], s);
            den2[t] += s;
        }
    }
    __syncthreads();
    // masked store (inclusive causal: j <= i)
#pragma unroll
    for (int ii = 0; ii < 8; ii++) {
        int i = ty * 8 + ii;
#pragma unroll
        for (int jj = 0; jj < 8; jj++) {
            int jc = tx + 16 * jj;
            Psm[i * 129 + jc] = (jc <= i) ? accP[ii][jj] : 0.f;
        }
    }
    __syncthreads();
    if (t < 128) {
        float s = den2[t];
        for (int j = 0; j < 128; j++) s += Psm[t * 129 + j];
        den_s[t] = s;
    }
    __syncthreads();

    // ----- intra: out = P_masked @ v -----
    float* v_s = buf;    // 128*129
    for (int i = t; i < 128 * 128; i += 256) {
        int r = i >> 7, d = i & 127;
        v_s[r * 129 + d] = g_v[vbase + i];
    }
    __syncthreads();
    float accO[8][8];
#pragma unroll
    for (int i = 0; i < 8; i++)
#pragma unroll
        for (int j = 0; j < 8; j++) accO[i][j] = 0.f;
    for (int j = 0; j < 128; j++) {
        float a[8], w[8];
#pragma unroll
        for (int ii = 0; ii < 8; ii++) a[ii] = Psm[(ty * 8 + ii) * 129 + j];
#pragma unroll
        for (int dd = 0; dd < 8; dd++) w[dd] = v_s[j * 129 + tx + 16 * dd];
#pragma unroll
        for (int ii = 0; ii < 8; ii++)
#pragma unroll
            for (int dd = 0; dd < 8; dd++)
                accO[ii][dd] = fmaf(a[ii], w[dd], accO[ii][dd]);
    }

    // ----- inter: out += phi_q @ KV_pre -----
    float* pq2  = buf;          // 128*33
    float* kv_s = buf + 4224;   // 32*129
    size_t kvbase = (((size_t)(b * HKVn + kvh)) * NCn + c) * (size_t)32768;
    for (int m0 = 0; m0 < 256; m0 += 32) {
        __syncthreads();
        for (int i = t; i < 128 * 32; i += 256) {
            int r = i >> 5, cc = i & 31;
            pq2[r * 33 + cc] = g_phiq[qbase + (size_t)r * 256 + m0 + cc];
        }
        for (int i = t; i < 32 * 128; i += 256) {
            int mm = i >> 7, d = i & 127;
            kv_s[mm * 129 + d] = g_kv[kvbase + (size_t)(m0 + mm) * 128 + d];
        }
        __syncthreads();
        for (int m = 0; m < 32; m++) {
            float a[8], w[8];
#pragma unroll
            for (int ii = 0; ii < 8; ii++) a[ii] = pq2[(ty * 8 + ii) * 33 + m];
#pragma unroll
            for (int dd = 0; dd < 8; dd++) w[dd] = kv_s[m * 129 + tx + 16 * dd];
#pragma unroll
            for (int ii = 0; ii < 8; ii++)
#pragma unroll
                for (int dd = 0; dd < 8; dd++)
                    accO[ii][dd] = fmaf(a[ii], w[dd], accO[ii][dd]);
        }
    }
    __syncthreads();
#pragma unroll
    for (int ii = 0; ii < 8; ii++) {
        int i = ty * 8 + ii;
        int s = c * 128 + i;
        float dn = den_s[i] + 1e-6f;
#pragma unroll
        for (int dd = 0; dd < 8; dd++) {
            int d = tx + 16 * dd;
            g_attn[((size_t)b * Ss + s) * 2048 + (size_t)h * 128 + d] = accO[ii][dd] / dn;
        }
    }
}

// ---------------- launch ------------------------------------------------------
extern "C" void kernel_launch(void* const* d_in, const int* in_sizes, int n_in,
                              void* d_out, int out_size)
{
    const float* hs   = (const float*)d_in[0];
    const float* cosp = (const float*)d_in[1];
    const float* sinp = (const float*)d_in[2];
    const float* wq   = (const float*)d_in[3];
    const float* wk   = (const float*)d_in[4];
    const float* wv   = (const float*)d_in[5];
    const float* wo   = (const float*)d_in[6];
    const float* proj = (const float*)d_in[7];
    float* out = (float*)d_out;

    float *pq_, *pk_, *pv_, *pphiq, *pphik, *ppart, *pattn;
    cudaGetSymbolAddress((void**)&pq_,   g_q);
    cudaGetSymbolAddress((void**)&pk_,   g_k);
    cudaGetSymbolAddress((void**)&pv_,   g_v);
    cudaGetSymbolAddress((void**)&pphiq, g_phiq);
    cudaGetSymbolAddress((void**)&pphik, g_phik);
    cudaGetSymbolAddress((void**)&ppart, g_part);
    cudaGetSymbolAddress((void**)&pattn, g_attn);

    cudaFuncSetAttribute(featmap_kernel, cudaFuncAttributeMaxDynamicSharedMemorySize, 165120);
    cudaFuncSetAttribute(attn_kernel,    cudaFuncAttributeMaxDynamicSharedMemorySize, 132608);

    dim3 blk(256);
    // QKV projections (head-split transposed outputs)
    gemm_tn<<<dim3(2048 / 64, 8192 / 64), blk>>>(hs, wq, pq_, 8192, 2048, 2048, 1, 16);
    gemm_tn<<<dim3(1024 / 64, 8192 / 64), blk>>>(hs, wk, pk_, 8192, 1024, 2048, 1, 8);
    gemm_tn<<<dim3(1024 / 64, 8192 / 64), blk>>>(hs, wv, pv_, 8192, 1024, 2048, 1, 8);
    // RoPE
    rope_kernel<<<(Bb * Hh * Ss * 64) / 256, 256>>>(pq_, cosp, sinp, Hh);
    rope_kernel<<<(Bb * HKVn * Ss * 64) / 256, 256>>>(pk_, cosp, sinp, HKVn);
    // feature maps
    featmap_kernel<<<(Bb * Hh * Ss) / 64, 256, 165120>>>(pq_, proj, pphiq, ppart, 1);
    featmap_kernel<<<(Bb * HKVn * Ss) / 64, 256, 165120>>>(pk_, proj, pphik, ppart, 0);
    reduce_max_kernel<<<1, 256>>>(ppart, (Bb * HKVn * Ss) / 64);
    expk_kernel<<<(Bb * HKVn * Ss * Mm) / 256, 256>>>(pphik, (size_t)Bb * HKVn * Ss * Mm);
    // chunk states
    kvchunk_kernel<<<dim3(2, NCn, Bb * HKVn), 256>>>();
    kvprefix_kernel<<<dim3(128, Bb * HKVn), 256>>>();
    ksum_kernel<<<dim3(NCn, Bb * HKVn), 256>>>();
    ksumprefix_kernel<<<Bb * HKVn, 256>>>();
    // attention
    attn_kernel<<<dim3(NCn, Hh, Bb), 256, 132608>>>();
    // output projection
    gemm_tn<<<dim3(2048 / 64, 8192 / 64), blk>>>(pattn, wo, out, 8192, 2048, 2048, 0, 0);
}

// round 4
// speedup vs baseline: 2.5967x; 2.5967x over previous
#include <cuda_runtime.h>
#include <cuda_bf16.h>
#include <cstdint>

#define Bb 2
#define Ss 4096
#define HIDN 2048
#define Hh 16
#define HKVn 8
#define Dd 128
#define Mm 256
#define NCn 32
#define CHn 128

// ---------------- scratch -----------------------------------------------------
__device__ float g_q[(size_t)Bb * Hh * Ss * Dd];
__device__ float g_k[(size_t)Bb * HKVn * Ss * Dd];
__device__ float g_v[(size_t)Bb * HKVn * Ss * Dd];
__device__ float g_phiq[(size_t)Bb * Hh * Ss * Mm];
__device__ float g_phik[(size_t)Bb * HKVn * Ss * Mm];
__device__ float g_kv[(size_t)Bb * HKVn * NCn * Mm * Dd];
__device__ float g_ksum[(size_t)Bb * HKVn * NCn * Mm];
__device__ float g_attn[(size_t)Bb * Ss * Hh * Dd];
__device__ float g_part[4096];
__device__ float g_zmax;

// bf16 hi/lo splits (A buffer reused for hs then attn)
__device__ __nv_bfloat16 g_ah[16777216], g_al[16777216];
__device__ __nv_bfloat16 g_wqh[4194304], g_wql[4194304];
__device__ __nv_bfloat16 g_wkh[2097152], g_wkl[2097152];
__device__ __nv_bfloat16 g_wvh[2097152], g_wvl[2097152];
__device__ __nv_bfloat16 g_woh[4194304], g_wol[4194304];

// ---------------- helpers -----------------------------------------------------
__device__ __forceinline__ uint32_t smem_u32(const void* p) {
    uint32_t a;
    asm("{ .reg .u64 t; cvta.to.shared.u64 t, %1; cvt.u32.u64 %0, t; }" : "=r"(a) : "l"(p));
    return a;
}
__device__ __forceinline__ void cp16(uint32_t dst, const void* src) {
    asm volatile("cp.async.cg.shared.global [%0], [%1], 16;" :: "r"(dst), "l"(src));
}
__device__ __forceinline__ void cp_commit() { asm volatile("cp.async.commit_group;"); }
__device__ __forceinline__ void cp_wait1()  { asm volatile("cp.async.wait_group 1;"); }

__device__ __forceinline__ void ldmx4(uint32_t* r, uint32_t addr) {
    asm volatile("ldmatrix.sync.aligned.m8n8.x4.shared.b16 {%0,%1,%2,%3}, [%4];"
                 : "=r"(r[0]), "=r"(r[1]), "=r"(r[2]), "=r"(r[3]) : "r"(addr));
}
__device__ __forceinline__ void mma16816(float* c, const uint32_t* a, const uint32_t* b) {
    asm volatile(
        "mma.sync.aligned.m16n8k16.row.col.f32.bf16.bf16.f32 "
        "{%0,%1,%2,%3},{%4,%5,%6,%7},{%8,%9},{%0,%1,%2,%3};"
        : "+f"(c[0]), "+f"(c[1]), "+f"(c[2]), "+f"(c[3])
        : "r"(a[0]), "r"(a[1]), "r"(a[2]), "r"(a[3]), "r"(b[0]), "r"(b[1]));
}

// ---------------- fp32 -> bf16 hi/lo split -----------------------------------
__global__ void split_kernel(const float* __restrict__ x, __nv_bfloat16* __restrict__ hi,
                             __nv_bfloat16* __restrict__ lo, int n4)
{
    int i = blockIdx.x * 256 + threadIdx.x;
    if (i < n4) {
        float4 v = ((const float4*)x)[i];
        __nv_bfloat16 h0 = __float2bfloat16(v.x);
        __nv_bfloat16 h1 = __float2bfloat16(v.y);
        __nv_bfloat16 h2 = __float2bfloat16(v.z);
        __nv_bfloat16 h3 = __float2bfloat16(v.w);
        ushort4 hh, ll;
        hh.x = __bfloat16_as_ushort(h0); hh.y = __bfloat16_as_ushort(h1);
        hh.z = __bfloat16_as_ushort(h2); hh.w = __bfloat16_as_ushort(h3);
        ll.x = __bfloat16_as_ushort(__float2bfloat16(v.x - __bfloat162float(h0)));
        ll.y = __bfloat16_as_ushort(__float2bfloat16(v.y - __bfloat162float(h1)));
        ll.z = __bfloat16_as_ushort(__float2bfloat16(v.z - __bfloat162float(h2)));
        ll.w = __bfloat16_as_ushort(__float2bfloat16(v.w - __bfloat162float(h3)));
        ((ushort4*)hi)[i] = hh;
        ((ushort4*)lo)[i] = ll;
    }
}

// ---------------- HMMA bf16x3 GEMM: C[r,c] = sum_k A[r,k]*W[c,k] -------------
// K fixed = 2048, tile 128x128, 8 warps (2m x 4n), warp tile 64x32.
// k-chunk 32, double-buffered cp.async. smem rows padded to 80B (40 bf16).
// mode 0: C row-major [M,N]. mode 1: head-split to (b,h,s,d).
#define STG_BYTES 40960     // 4 tiles * 128 * 80
#define TILE_BYTES 10240    // 128 * 80
__global__ void __launch_bounds__(256, 1)
hmma_gemm(const __nv_bfloat16* __restrict__ Ah, const __nv_bfloat16* __restrict__ Al,
          const __nv_bfloat16* __restrict__ Wh, const __nv_bfloat16* __restrict__ Wl,
          float* __restrict__ C, int N, int mode, int NH)
{
    extern __shared__ char smem[];
    const uint32_t sb = smem_u32(smem);
    const int t = threadIdx.x, lane = t & 31, wid = t >> 5;
    const int wm = wid >> 2, wn = wid & 3;
    const int row0 = blockIdx.y * 128, col0 = blockIdx.x * 128;

    const __nv_bfloat16* gA[2] = { Ah + (size_t)row0 * 2048, Al + (size_t)row0 * 2048 };
    const __nv_bfloat16* gB[2] = { Wh + (size_t)col0 * 2048, Wl + (size_t)col0 * 2048 };

    // issue one k-chunk (32 cols) of all 4 tiles into stage s
    auto issue = [&](int s, int kc) {
        uint32_t base = sb + s * STG_BYTES;
#pragma unroll
        for (int idx = t; idx < 2048; idx += 256) {
            int tile = idx >> 9;          // 0 Ah, 1 Al, 2 Bh, 3 Bl
            int rem = idx & 511;
            int r = rem >> 2, c = rem & 3;
            const __nv_bfloat16* src =
                (tile < 2 ? gA[tile] : gB[tile - 2]) + (size_t)r * 2048 + kc * 32 + c * 8;
            cp16(base + tile * TILE_BYTES + r * 80 + c * 16, src);
        }
        cp_commit();
    };

    float acc[4][4][4];
#pragma unroll
    for (int i = 0; i < 4; i++)
#pragma unroll
        for (int j = 0; j < 4; j++)
#pragma unroll
            for (int k = 0; k < 4; k++) acc[i][j][k] = 0.f;

    issue(0, 0);
    issue(1, 1);

    // per-lane ldmatrix byte offsets (within a tile)
    const int arow = wm * 64 + (lane & 15);
    const int acol = (lane >> 4) * 16;            // +16B for k+8 matrices
    const int brow = wn * 32 + (lane & 7) + ((lane >> 4) & 1) * 8;
    const int bcol = ((lane >> 3) & 1) * 16;

    for (int kc = 0; kc < 64; kc++) {
        cp_wait1();
        __syncthreads();
        uint32_t base = sb + (kc & 1) * STG_BYTES;
        uint32_t aH = base, aL = base + TILE_BYTES;
        uint32_t bH = base + 2 * TILE_BYTES, bL = base + 3 * TILE_BYTES;
#pragma unroll
        for (int ks = 0; ks < 2; ks++) {
            uint32_t kb = ks * 32;
            uint32_t ah[4][4], al[4][4], bh[4][2], bl[4][2];
#pragma unroll
            for (int i = 0; i < 4; i++) {
                uint32_t off = (uint32_t)(arow + i * 16) * 80 + kb + acol;
                ldmx4(ah[i], aH + off);
                ldmx4(al[i], aL + off);
            }
#pragma unroll
            for (int nt = 0; nt < 2; nt++) {
                uint32_t off = (uint32_t)(brow + nt * 16) * 80 + kb + bcol;
                uint32_t rh[4], rl[4];
                ldmx4(rh, bH + off);
                ldmx4(rl, bL + off);
                bh[nt * 2][0] = rh[0]; bh[nt * 2][1] = rh[1];
                bh[nt * 2 + 1][0] = rh[2]; bh[nt * 2 + 1][1] = rh[3];
                bl[nt * 2][0] = rl[0]; bl[nt * 2][1] = rl[1];
                bl[nt * 2 + 1][0] = rl[2]; bl[nt * 2 + 1][1] = rl[3];
            }
#pragma unroll
            for (int i = 0; i < 4; i++)
#pragma unroll
                for (int j = 0; j < 4; j++) {
                    mma16816(acc[i][j], ah[i], bh[j]);
                    mma16816(acc[i][j], ah[i], bl[j]);
                    mma16816(acc[i][j], al[i], bh[j]);
                }
        }
        __syncthreads();
        if (kc + 2 < 64) issue(kc & 1, kc + 2);
        else cp_commit();   // keep group counting consistent
    }

    // epilogue
#pragma unroll
    for (int i = 0; i < 4; i++) {
        int m = wm * 64 + i * 16 + (lane >> 2);
#pragma unroll
        for (int j = 0; j < 4; j++) {
            int n = wn * 32 + j * 8 + (lane & 3) * 2;
#pragma unroll
            for (int half = 0; half < 2; half++) {
                int mr = m + half * 8;
                float2 v;
                v.x = acc[i][j][half * 2 + 0];
                v.y = acc[i][j][half * 2 + 1];
                if (mode == 0) {
                    *(float2*)(C + (size_t)(row0 + mr) * N + col0 + n) = v;
                } else {
                    int gr = row0 + mr;
                    int b = gr >> 12, srow = gr & 4095;
                    int h = col0 >> 7;
                    *(float2*)(C + ((((size_t)b * NH + h) * 4096 + srow) << 7) + n) = v;
                }
            }
        }
    }
}

// ---------------- RoPE in-place on (b,h,s,d) ---------------------------------
__global__ void rope_kernel(float* __restrict__ X, const float* __restrict__ cosp,
                            const float* __restrict__ sinp, int NH)
{
    size_t idx = (size_t)blockIdx.x * blockDim.x + threadIdx.x;
    int d = idx & 63;
    size_t r = idx >> 6;
    int s = (int)(r % Ss); r /= Ss;
    int h = (int)(r % NH); int b = (int)(r / NH);
    size_t base = (((size_t)b * NH + h) * Ss + s) << 7;
    float x1 = X[base + d], x2 = X[base + d + 64];
    size_t cb = (((size_t)b * Ss + s) << 7);
    float c1 = cosp[cb + d],      s1 = sinp[cb + d];
    float c2 = cosp[cb + d + 64], s2 = sinp[cb + d + 64];
    X[base + d]      = fmaf(x1, c1, -x2 * s1);
    X[base + d + 64] = fmaf(x2, c2,  x1 * s2);
}

// ---------------- feature map ------------------------------------------------
__global__ void featmap_kernel(const float* __restrict__ X, const float* __restrict__ proj,
                               float* __restrict__ out, float* __restrict__ partials, int isq)
{
    extern __shared__ float sm[];
    float* Ps = sm;               // 256*129
    float* Xs = sm + 256 * 129;   // 64*129
    int t = threadIdx.x;
    int tx = t & 15, ty = t >> 4;
    size_t row0 = (size_t)blockIdx.x * 64;

    for (int i = t; i < 256 * 128; i += 256) {
        int m = i >> 7, d = i & 127;
        Ps[m * 129 + d] = proj[i];
    }
    const float sc = 0.29730177875068026f;
    for (int i = t; i < 64 * 128; i += 256) {
        int r = i >> 7, d = i & 127;
        Xs[r * 129 + d] = X[(row0 + r) * 128 + d] * sc;
    }
    __syncthreads();

    float acc[4][16];
#pragma unroll
    for (int i = 0; i < 4; i++)
#pragma unroll
        for (int j = 0; j < 16; j++) acc[i][j] = 0.f;
    float sq[4] = {0.f, 0.f, 0.f, 0.f};

    for (int d = 0; d < 128; d++) {
        float a[4];
#pragma unroll
        for (int i = 0; i < 4; i++) {
            a[i] = Xs[(ty * 4 + i) * 129 + d];
            sq[i] = fmaf(a[i], a[i], sq[i]);
        }
#pragma unroll
        for (int j = 0; j < 16; j++) {
            float p = Ps[(tx + 16 * j) * 129 + d];
#pragma unroll
            for (int i = 0; i < 4; i++) acc[i][j] = fmaf(a[i], p, acc[i][j]);
        }
    }
    float rmax[4];
#pragma unroll
    for (int i = 0; i < 4; i++) {
        float hlf = 0.5f * sq[i];
        float mx = -1e30f;
#pragma unroll
        for (int j = 0; j < 16; j++) {
            acc[i][j] -= hlf;
            mx = fmaxf(mx, acc[i][j]);
        }
        rmax[i] = mx;
    }
    if (isq) {
#pragma unroll
        for (int o = 1; o < 16; o <<= 1)
#pragma unroll
            for (int i = 0; i < 4; i++)
                rmax[i] = fmaxf(rmax[i], __shfl_xor_sync(0xffffffffu, rmax[i], o));
#pragma unroll
        for (int i = 0; i < 4; i++) {
            size_t ro = (row0 + ty * 4 + i) * 256;
#pragma unroll
            for (int j = 0; j < 16; j++)
                out[ro + tx + 16 * j] = expf(acc[i][j] - rmax[i]) * 0.0625f + 1e-6f;
        }
    } else {
#pragma unroll
        for (int i = 0; i < 4; i++) {
            size_t ro = (row0 + ty * 4 + i) * 256;
#pragma unroll
            for (int j = 0; j < 16; j++)
                out[ro + tx + 16 * j] = acc[i][j];
        }
        __shared__ float red[256];
        float mx = fmaxf(fmaxf(rmax[0], rmax[1]), fmaxf(rmax[2], rmax[3]));
        red[t] = mx;
        __syncthreads();
        for (int o = 128; o > 0; o >>= 1) {
            if (t < o) red[t] = fmaxf(red[t], red[t + o]);
            __syncthreads();
        }
        if (t == 0) partials[blockIdx.x] = red[0];
    }
}

__global__ void reduce_max_kernel(const float* __restrict__ partials, int n)
{
    __shared__ float red[256];
    int t = threadIdx.x;
    float mx = -1e30f;
    for (int i = t; i < n; i += 256) mx = fmaxf(mx, partials[i]);
    red[t] = mx; __syncthreads();
    for (int o = 128; o > 0; o >>= 1) {
        if (t < o) red[t] = fmaxf(red[t], red[t + o]);
        __syncthreads();
    }
    if (t == 0) g_zmax = red[0];
}

__global__ void expk_kernel(float* __restrict__ Z, size_t n)
{
    size_t i = (size_t)blockIdx.x * blockDim.x + threadIdx.x;
    if (i < n) Z[i] = expf(Z[i] - g_zmax) * 0.0625f + 1e-6f;
}

// ---------------- per-chunk KV = phi_k^T @ v ---------------------------------
__global__ void kvchunk_kernel()
{
    __shared__ float pks[32 * 256];
    __shared__ float vs[32 * 64];
    int dh = blockIdx.x;
    int c  = blockIdx.y;
    int bh = blockIdx.z;
    int t = threadIdx.x, tx = t & 15, ty = t >> 4;
    const float* pk = g_phik + ((size_t)bh * Ss + (size_t)c * 128) * 256;
    const float* vv = g_v    + ((size_t)bh * Ss + (size_t)c * 128) * 128 + dh * 64;
    float acc[16][4];
#pragma unroll
    for (int a = 0; a < 16; a++)
#pragma unroll
        for (int b2 = 0; b2 < 4; b2++) acc[a][b2] = 0.f;

    for (int j0 = 0; j0 < 128; j0 += 32) {
        __syncthreads();
        for (int i = t; i < 32 * 256; i += 256) pks[i] = pk[(size_t)j0 * 256 + i];
        for (int i = t; i < 32 * 64; i += 256) {
            int j = i >> 6, d = i & 63;
            vs[i] = vv[(size_t)(j0 + j) * 128 + d];
        }
        __syncthreads();
        for (int j = 0; j < 32; j++) {
            float a[16], b4[4];
#pragma unroll
            for (int mi = 0; mi < 16; mi++) a[mi] = pks[j * 256 + tx + 16 * mi];
#pragma unroll
            for (int di = 0; di < 4; di++) b4[di] = vs[j * 64 + ty * 4 + di];
#pragma unroll
            for (int mi = 0; mi < 16; mi++)
#pragma unroll
                for (int di = 0; di < 4; di++)
                    acc[mi][di] = fmaf(a[mi], b4[di], acc[mi][di]);
        }
    }
    float* outp = g_kv + (((size_t)bh * NCn + c) * 256) * 128 + dh * 64;
#pragma unroll
    for (int mi = 0; mi < 16; mi++)
#pragma unroll
        for (int di = 0; di < 4; di++)
            outp[(size_t)(tx + 16 * mi) * 128 + ty * 4 + di] = acc[mi][di];
}

__global__ void kvprefix_kernel()
{
    int e = blockIdx.x * 256 + threadIdx.x;
    int bh = blockIdx.y;
    size_t base = (size_t)bh * NCn * 32768 + e;
    float run = 0.f;
    for (int c = 0; c < NCn; c++) {
        size_t p = base + (size_t)c * 32768;
        float v = g_kv[p];
        g_kv[p] = run;
        run += v;
    }
}

__global__ void ksum_kernel()
{
    int c = blockIdx.x, bh = blockIdx.y, m = threadIdx.x;
    const float* pk = g_phik + ((size_t)bh * Ss + (size_t)c * 128) * 256;
    float s = 0.f;
    for (int j = 0; j < 128; j++) s += pk[(size_t)j * 256 + m];
    g_ksum[((size_t)bh * NCn + c) * 256 + m] = s;
}

__global__ void ksumprefix_kernel()
{
    int bh = blockIdx.x, m = threadIdx.x;
    float run = 0.f;
    for (int c = 0; c < NCn; c++) {
        size_t p = ((size_t)bh * NCn + c) * 256 + m;
        float v = g_ksum[p];
        g_ksum[p] = run;
        run += v;
    }
}

// ---------------- attention main ---------------------------------------------
__global__ void attn_kernel()
{
    extern __shared__ float sm[];
    float* Psm   = sm;
    float* buf   = sm + 16512;
    float* den_s = sm + 33024;
    int t = threadIdx.x, tx = t & 15, ty = t >> 4;
    int c = blockIdx.x, h = blockIdx.y, b = blockIdx.z;
    int kvh = h >> 1;
    size_t qbase = (((size_t)(b * Hh + h)) * Ss + (size_t)c * 128) * 256;
    size_t kbase = (((size_t)(b * HKVn + kvh)) * Ss + (size_t)c * 128) * 256;
    size_t vbase = (((size_t)(b * HKVn + kvh)) * Ss + (size_t)c * 128) * 128;

    float* pq_s = buf;
    float* pk_s = buf + 4224;
    float* ksp  = buf + 8448;
    float* den2 = buf + 8704;

    if (t < 128) den2[t] = 0.f;
    if (t < 256) ksp[t] = g_ksum[(((size_t)(b * HKVn + kvh)) * NCn + c) * 256 + t];

    float accP[8][8];
#pragma unroll
    for (int i = 0; i < 8; i++)
#pragma unroll
        for (int j = 0; j < 8; j++) accP[i][j] = 0.f;

    for (int m0 = 0; m0 < 256; m0 += 32) {
        __syncthreads();
        for (int i = t; i < 128 * 32; i += 256) {
            int r = i >> 5, cc = i & 31;
            pq_s[r * 33 + cc] = g_phiq[qbase + (size_t)r * 256 + m0 + cc];
            pk_s[r * 33 + cc] = g_phik[kbase + (size_t)r * 256 + m0 + cc];
        }
        __syncthreads();
        for (int m = 0; m < 32; m++) {
            float a[8], w[8];
#pragma unroll
            for (int ii = 0; ii < 8; ii++) a[ii] = pq_s[(ty * 8 + ii) * 33 + m];
#pragma unroll
            for (int jj = 0; jj < 8; jj++) w[jj] = pk_s[(tx + 16 * jj) * 33 + m];
#pragma unroll
            for (int ii = 0; ii < 8; ii++)
#pragma unroll
                for (int jj = 0; jj < 8; jj++)
                    accP[ii][jj] = fmaf(a[ii], w[jj], accP[ii][jj]);
        }
        if (t < 128) {
            float s = 0.f;
            for (int m = 0; m < 32; m++) s = fmaf(pq_s[t * 33 + m], ksp[m0 + m], s);
            den2[t] += s;
        }
    }
    __syncthreads();
#pragma unroll
    for (int ii = 0; ii < 8; ii++) {
        int i = ty * 8 + ii;
#pragma unroll
        for (int jj = 0; jj < 8; jj++) {
            int jc = tx + 16 * jj;
            Psm[i * 129 + jc] = (jc <= i) ? accP[ii][jj] : 0.f;
        }
    }
    __syncthreads();
    if (t < 128) {
        float s = den2[t];
        for (int j = 0; j < 128; j++) s += Psm[t * 129 + j];
        den_s[t] = s;
    }
    __syncthreads();

    float* v_s = buf;
    for (int i = t; i < 128 * 128; i += 256) {
        int r = i >> 7, d = i & 127;
        v_s[r * 129 + d] = g_v[vbase + i];
    }
    __syncthreads();
    float accO[8][8];
#pragma unroll
    for (int i = 0; i < 8; i++)
#pragma unroll
        for (int j = 0; j < 8; j++) accO[i][j] = 0.f;
    for (int j = 0; j < 128; j++) {
        float a[8], w[8];
#pragma unroll
        for (int ii = 0; ii < 8; ii++) a[ii] = Psm[(ty * 8 + ii) * 129 + j];
#pragma unroll
        for (int dd = 0; dd < 8; dd++) w[dd] = v_s[j * 129 + tx + 16 * dd];
#pragma unroll
        for (int ii = 0; ii < 8; ii++)
#pragma unroll
            for (int dd = 0; dd < 8; dd++)
                accO[ii][dd] = fmaf(a[ii], w[dd], accO[ii][dd]);
    }

    float* pq2  = buf;
    float* kv_s = buf + 4224;
    size_t kvbase = (((size_t)(b * HKVn + kvh)) * NCn + c) * (size_t)32768;
    for (int m0 = 0; m0 < 256; m0 += 32) {
        __syncthreads();
        for (int i = t; i < 128 * 32; i += 256) {
            int r = i >> 5, cc = i & 31;
            pq2[r * 33 + cc] = g_phiq[qbase + (size_t)r * 256 + m0 + cc];
        }
        for (int i = t; i < 32 * 128; i += 256) {
            int mm = i >> 7, d = i & 127;
            kv_s[mm * 129 + d] = g_kv[kvbase + (size_t)(m0 + mm) * 128 + d];
        }
        __syncthreads();
        for (int m = 0; m < 32; m++) {
            float a[8], w[8];
#pragma unroll
            for (int ii = 0; ii < 8; ii++) a[ii] = pq2[(ty * 8 + ii) * 33 + m];
#pragma unroll
            for (int dd = 0; dd < 8; dd++) w[dd] = kv_s[m * 129 + tx + 16 * dd];
#pragma unroll
            for (int ii = 0; ii < 8; ii++)
#pragma unroll
                for (int dd = 0; dd < 8; dd++)
                    accO[ii][dd] = fmaf(a[ii], w[dd], accO[ii][dd]);
        }
    }
    __syncthreads();
#pragma unroll
    for (int ii = 0; ii < 8; ii++) {
        int i = ty * 8 + ii;
        int s = c * 128 + i;
        float dn = den_s[i] + 1e-6f;
#pragma unroll
        for (int dd = 0; dd < 8; dd++) {
            int d = tx + 16 * dd;
            g_attn[((size_t)b * Ss + s) * 2048 + (size_t)h * 128 + d] = accO[ii][dd] / dn;
        }
    }
}

// ---------------- launch ------------------------------------------------------
extern "C" void kernel_launch(void* const* d_in, const int* in_sizes, int n_in,
                              void* d_out, int out_size)
{
    const float* hs   = (const float*)d_in[0];
    const float* cosp = (const float*)d_in[1];
    const float* sinp = (const float*)d_in[2];
    const float* wq   = (const float*)d_in[3];
    const float* wk   = (const float*)d_in[4];
    const float* wv   = (const float*)d_in[5];
    const float* wo   = (const float*)d_in[6];
    const float* proj = (const float*)d_in[7];
    float* out = (float*)d_out;

    float *pq_, *pk_, *pv_, *pphiq, *pphik, *ppart, *pattn;
    cudaGetSymbolAddress((void**)&pq_,   g_q);
    cudaGetSymbolAddress((void**)&pk_,   g_k);
    cudaGetSymbolAddress((void**)&pv_,   g_v);
    cudaGetSymbolAddress((void**)&pphiq, g_phiq);
    cudaGetSymbolAddress((void**)&pphik, g_phik);
    cudaGetSymbolAddress((void**)&ppart, g_part);
    cudaGetSymbolAddress((void**)&pattn, g_attn);
    __nv_bfloat16 *ah, *al, *wqh, *wql, *wkh, *wkl, *wvh, *wvl, *woh, *wol;
    cudaGetSymbolAddress((void**)&ah,  g_ah);
    cudaGetSymbolAddress((void**)&al,  g_al);
    cudaGetSymbolAddress((void**)&wqh, g_wqh);
    cudaGetSymbolAddress((void**)&wql, g_wql);
    cudaGetSymbolAddress((void**)&wkh, g_wkh);
    cudaGetSymbolAddress((void**)&wkl, g_wkl);
    cudaGetSymbolAddress((void**)&wvh, g_wvh);
    cudaGetSymbolAddress((void**)&wvl, g_wvl);
    cudaGetSymbolAddress((void**)&woh, g_woh);
    cudaGetSymbolAddress((void**)&wol, g_wol);

    cudaFuncSetAttribute(featmap_kernel, cudaFuncAttributeMaxDynamicSharedMemorySize, 165120);
    cudaFuncSetAttribute(attn_kernel,    cudaFuncAttributeMaxDynamicSharedMemorySize, 132608);
    cudaFuncSetAttribute(hmma_gemm,      cudaFuncAttributeMaxDynamicSharedMemorySize, 2 * STG_BYTES);

    // splits
    split_kernel<<<16384, 256>>>(hs, ah, al, 4194304);
    split_kernel<<<4096,  256>>>(wq, wqh, wql, 1048576);
    split_kernel<<<2048,  256>>>(wk, wkh, wkl, 524288);
    split_kernel<<<2048,  256>>>(wv, wvh, wvl, 524288);
    split_kernel<<<4096,  256>>>(wo, woh, wol, 1048576);

    // QKV projections on tensor cores (mma.sync)
    hmma_gemm<<<dim3(16, 64), 256, 2 * STG_BYTES>>>(ah, al, wqh, wql, pq_, 2048, 1, 16);
    hmma_gemm<<<dim3(8,  64), 256, 2 * STG_BYTES>>>(ah, al, wkh, wkl, pk_, 1024, 1, 8);
    hmma_gemm<<<dim3(8,  64), 256, 2 * STG_BYTES>>>(ah, al, wvh, wvl, pv_, 1024, 1, 8);

    // RoPE
    rope_kernel<<<(Bb * Hh * Ss * 64) / 256, 256>>>(pq_, cosp, sinp, Hh);
    rope_kernel<<<(Bb * HKVn * Ss * 64) / 256, 256>>>(pk_, cosp, sinp, HKVn);
    // feature maps
    featmap_kernel<<<(Bb * Hh * Ss) / 64, 256, 165120>>>(pq_, proj, pphiq, ppart, 1);
    featmap_kernel<<<(Bb * HKVn * Ss) / 64, 256, 165120>>>(pk_, proj, pphik, ppart, 0);
    reduce_max_kernel<<<1, 256>>>(ppart, (Bb * HKVn * Ss) / 64);
    expk_kernel<<<(Bb * HKVn * Ss * Mm) / 256, 256>>>(pphik, (size_t)Bb * HKVn * Ss * Mm);
    // chunk states
    kvchunk_kernel<<<dim3(2, NCn, Bb * HKVn), 256>>>();
    kvprefix_kernel<<<dim3(128, Bb * HKVn), 256>>>();
    ksum_kernel<<<dim3(NCn, Bb * HKVn), 256>>>();
    ksumprefix_kernel<<<Bb * HKVn, 256>>>();
    // attention
    attn_kernel<<<dim3(NCn, Hh, Bb), 256, 132608>>>();
    // output projection
    split_kernel<<<16384, 256>>>(pattn, ah, al, 4194304);
    hmma_gemm<<<dim3(16, 64), 256, 2 * STG_BYTES>>>(ah, al, woh, wol, out, 2048, 0, 0);
}

// round 5
// speedup vs baseline: 3.2022x; 1.2332x over previous
#include <cuda_runtime.h>
#include <cuda_bf16.h>
#include <cstdint>

#define Bb 2
#define Ss 4096
#define HIDN 2048
#define Hh 16
#define HKVn 8
#define Dd 128
#define Mm 256
#define NCn 32

// ---------------- scratch -----------------------------------------------------
__device__ float g_q[(size_t)Bb * Hh * Ss * Dd];
__device__ float g_k[(size_t)Bb * HKVn * Ss * Dd];
__device__ float g_v[(size_t)Bb * HKVn * Ss * Dd];
__device__ float g_phik[(size_t)Bb * HKVn * Ss * Mm];          // z then phi (fp32)
__device__ float g_kv[(size_t)Bb * HKVn * NCn * Mm * Dd];
__device__ float g_ksum[(size_t)Bb * HKVn * NCn * Mm];
__device__ float g_attn[(size_t)Bb * Ss * Hh * Dd];
__device__ float g_part[4096];
__device__ float g_zmax;

// bf16 hi/lo operands
__device__ __nv_bfloat16 g_ah[16777216], g_al[16777216];
__device__ __nv_bfloat16 g_wqh[4194304], g_wql[4194304];
__device__ __nv_bfloat16 g_wkh[2097152], g_wkl[2097152];
__device__ __nv_bfloat16 g_wvh[2097152], g_wvl[2097152];
__device__ __nv_bfloat16 g_woh[4194304], g_wol[4194304];
__device__ __nv_bfloat16 g_phiqh[33554432], g_phiql[33554432];
__device__ __nv_bfloat16 g_phikh[16777216], g_phikl[16777216];
__device__ __nv_bfloat16 g_vth[8388608],  g_vtl[8388608];      // [bh, d, s]
__device__ __nv_bfloat16 g_kvth[16777216], g_kvtl[16777216];   // [bh, c, d, m]

// ---------------- helpers -----------------------------------------------------
__device__ __forceinline__ uint32_t smem_u32(const void* p) {
    uint32_t a;
    asm("{ .reg .u64 t; cvta.to.shared.u64 t, %1; cvt.u32.u64 %0, t; }" : "=r"(a) : "l"(p));
    return a;
}
__device__ __forceinline__ void cp16(uint32_t dst, const void* src) {
    asm volatile("cp.async.cg.shared.global [%0], [%1], 16;" :: "r"(dst), "l"(src));
}
__device__ __forceinline__ void cp_commit() { asm volatile("cp.async.commit_group;"); }
__device__ __forceinline__ void cp_wait1()  { asm volatile("cp.async.wait_group 1;"); }
__device__ __forceinline__ void cp_wait0()  { asm volatile("cp.async.wait_group 0;"); }

__device__ __forceinline__ void ldmx4(uint32_t* r, uint32_t addr) {
    asm volatile("ldmatrix.sync.aligned.m8n8.x4.shared.b16 {%0,%1,%2,%3}, [%4];"
                 : "=r"(r[0]), "=r"(r[1]), "=r"(r[2]), "=r"(r[3]) : "r"(addr));
}
__device__ __forceinline__ void mma16816(float* c, const uint32_t* a, const uint32_t* b) {
    asm volatile(
        "mma.sync.aligned.m16n8k16.row.col.f32.bf16.bf16.f32 "
        "{%0,%1,%2,%3},{%4,%5,%6,%7},{%8,%9},{%0,%1,%2,%3};"
        : "+f"(c[0]), "+f"(c[1]), "+f"(c[2]), "+f"(c[3])
        : "r"(a[0]), "r"(a[1]), "r"(a[2]), "r"(a[3]), "r"(b[0]), "r"(b[1]));
}
__device__ __forceinline__ void bsplit(float v, __nv_bfloat16& h, __nv_bfloat16& l) {
    h = __float2bfloat16(v);
    l = __float2bfloat16(v - __bfloat162float(h));
}

// ---------------- fp32 -> bf16 hi/lo split -----------------------------------
__global__ void split_kernel(const float* __restrict__ x, __nv_bfloat16* __restrict__ hi,
                             __nv_bfloat16* __restrict__ lo, int n4)
{
    int i = blockIdx.x * 256 + threadIdx.x;
    if (i < n4) {
        float4 v = ((const float4*)x)[i];
        __nv_bfloat16 h0, h1, h2, h3, l0, l1, l2, l3;
        bsplit(v.x, h0, l0); bsplit(v.y, h1, l1);
        bsplit(v.z, h2, l2); bsplit(v.w, h3, l3);
        ushort4 hh, ll;
        hh.x = __bfloat16_as_ushort(h0); hh.y = __bfloat16_as_ushort(h1);
        hh.z = __bfloat16_as_ushort(h2); hh.w = __bfloat16_as_ushort(h3);
        ll.x = __bfloat16_as_ushort(l0); ll.y = __bfloat16_as_ushort(l1);
        ll.z = __bfloat16_as_ushort(l2); ll.w = __bfloat16_as_ushort(l3);
        ((ushort4*)hi)[i] = hh;
        ((ushort4*)lo)[i] = ll;
    }
}

// ---------------- HMMA bf16x3 GEMM (projections) ------------------------------
#define STG_BYTES 40960
#define TILE_BYTES 10240
__global__ void __launch_bounds__(256, 1)
hmma_gemm(const __nv_bfloat16* __restrict__ Ah, const __nv_bfloat16* __restrict__ Al,
          const __nv_bfloat16* __restrict__ Wh, const __nv_bfloat16* __restrict__ Wl,
          float* __restrict__ C, int N, int mode, int NH)
{
    extern __shared__ char smem[];
    const uint32_t sb = smem_u32(smem);
    const int t = threadIdx.x, lane = t & 31, wid = t >> 5;
    const int wm = wid >> 2, wn = wid & 3;
    const int row0 = blockIdx.y * 128, col0 = blockIdx.x * 128;

    const __nv_bfloat16* gA[2] = { Ah + (size_t)row0 * 2048, Al + (size_t)row0 * 2048 };
    const __nv_bfloat16* gB[2] = { Wh + (size_t)col0 * 2048, Wl + (size_t)col0 * 2048 };

    auto issue = [&](int s, int kc) {
        uint32_t base = sb + s * STG_BYTES;
#pragma unroll
        for (int idx = t; idx < 2048; idx += 256) {
            int tile = idx >> 9;
            int rem = idx & 511;
            int r = rem >> 2, c = rem & 3;
            const __nv_bfloat16* src =
                (tile < 2 ? gA[tile] : gB[tile - 2]) + (size_t)r * 2048 + kc * 32 + c * 8;
            cp16(base + tile * TILE_BYTES + r * 80 + c * 16, src);
        }
        cp_commit();
    };

    float acc[4][4][4];
#pragma unroll
    for (int i = 0; i < 4; i++)
#pragma unroll
        for (int j = 0; j < 4; j++)
#pragma unroll
            for (int k = 0; k < 4; k++) acc[i][j][k] = 0.f;

    issue(0, 0);
    issue(1, 1);

    const int arow = wm * 64 + (lane & 15);
    const int acol = (lane >> 4) * 16;
    const int brow = wn * 32 + (lane & 7) + ((lane >> 4) & 1) * 8;
    const int bcol = ((lane >> 3) & 1) * 16;

    for (int kc = 0; kc < 64; kc++) {
        cp_wait1();
        __syncthreads();
        uint32_t base = sb + (kc & 1) * STG_BYTES;
        uint32_t aH = base, aL = base + TILE_BYTES;
        uint32_t bH = base + 2 * TILE_BYTES, bL = base + 3 * TILE_BYTES;
#pragma unroll
        for (int ks = 0; ks < 2; ks++) {
            uint32_t kb = ks * 32;
            uint32_t ah[4][4], al[4][4], bh[4][2], bl[4][2];
#pragma unroll
            for (int i = 0; i < 4; i++) {
                uint32_t off = (uint32_t)(arow + i * 16) * 80 + kb + acol;
                ldmx4(ah[i], aH + off);
                ldmx4(al[i], aL + off);
            }
#pragma unroll
            for (int nt = 0; nt < 2; nt++) {
                uint32_t off = (uint32_t)(brow + nt * 16) * 80 + kb + bcol;
                uint32_t rh[4], rl[4];
                ldmx4(rh, bH + off);
                ldmx4(rl, bL + off);
                bh[nt * 2][0] = rh[0]; bh[nt * 2][1] = rh[1];
                bh[nt * 2 + 1][0] = rh[2]; bh[nt * 2 + 1][1] = rh[3];
                bl[nt * 2][0] = rl[0]; bl[nt * 2][1] = rl[1];
                bl[nt * 2 + 1][0] = rl[2]; bl[nt * 2 + 1][1] = rl[3];
            }
#pragma unroll
            for (int i = 0; i < 4; i++)
#pragma unroll
                for (int j = 0; j < 4; j++) {
                    mma16816(acc[i][j], ah[i], bh[j]);
                    mma16816(acc[i][j], ah[i], bl[j]);
                    mma16816(acc[i][j], al[i], bh[j]);
                }
        }
        __syncthreads();
        if (kc + 2 < 64) issue(kc & 1, kc + 2);
        else cp_commit();
    }

#pragma unroll
    for (int i = 0; i < 4; i++) {
        int m = wm * 64 + i * 16 + (lane >> 2);
#pragma unroll
        for (int j = 0; j < 4; j++) {
            int n = wn * 32 + j * 8 + (lane & 3) * 2;
#pragma unroll
            for (int half = 0; half < 2; half++) {
                int mr = m + half * 8;
                float2 v;
                v.x = acc[i][j][half * 2 + 0];
                v.y = acc[i][j][half * 2 + 1];
                if (mode == 0) {
                    *(float2*)(C + (size_t)(row0 + mr) * N + col0 + n) = v;
                } else {
                    int b = (row0 + mr) >> 12, srow = (row0 + mr) & 4095;
                    int h = col0 >> 7;
                    *(float2*)(C + ((((size_t)b * NH + h) * 4096 + srow) << 7) + n) = v;
                }
            }
        }
    }
}

// ---------------- RoPE --------------------------------------------------------
__global__ void rope_kernel(float* __restrict__ X, const float* __restrict__ cosp,
                            const float* __restrict__ sinp, int NH)
{
    size_t idx = (size_t)blockIdx.x * blockDim.x + threadIdx.x;
    int d = idx & 63;
    size_t r = idx >> 6;
    int s = (int)(r % Ss); r /= Ss;
    int h = (int)(r % NH); int b = (int)(r / NH);
    size_t base = (((size_t)b * NH + h) * Ss + s) << 7;
    float x1 = X[base + d], x2 = X[base + d + 64];
    size_t cb = (((size_t)b * Ss + s) << 7);
    float c1 = cosp[cb + d],      s1 = sinp[cb + d];
    float c2 = cosp[cb + d + 64], s2 = sinp[cb + d + 64];
    X[base + d]      = fmaf(x1, c1, -x2 * s1);
    X[base + d + 64] = fmaf(x2, c2,  x1 * s2);
}

// ---------------- feature map -------------------------------------------------
// isq=1: write phi as bf16 hi/lo. isq=0: write raw z fp32 + block max.
__global__ void featmap_kernel(const float* __restrict__ X, const float* __restrict__ proj,
                               float* __restrict__ outf,
                               __nv_bfloat16* __restrict__ outh, __nv_bfloat16* __restrict__ outl,
                               float* __restrict__ partials, int isq)
{
    extern __shared__ float sm[];
    float* Ps = sm;               // 256*129
    float* Xs = sm + 256 * 129;   // 64*129
    int t = threadIdx.x;
    int tx = t & 15, ty = t >> 4;
    size_t row0 = (size_t)blockIdx.x * 64;

    for (int i = t; i < 256 * 128; i += 256) {
        int m = i >> 7, d = i & 127;
        Ps[m * 129 + d] = proj[i];
    }
    const float sc = 0.29730177875068026f;
    for (int i = t; i < 64 * 128; i += 256) {
        int r = i >> 7, d = i & 127;
        Xs[r * 129 + d] = X[(row0 + r) * 128 + d] * sc;
    }
    __syncthreads();

    float acc[4][16];
#pragma unroll
    for (int i = 0; i < 4; i++)
#pragma unroll
        for (int j = 0; j < 16; j++) acc[i][j] = 0.f;
    float sq[4] = {0.f, 0.f, 0.f, 0.f};

    for (int d = 0; d < 128; d++) {
        float a[4];
#pragma unroll
        for (int i = 0; i < 4; i++) {
            a[i] = Xs[(ty * 4 + i) * 129 + d];
            sq[i] = fmaf(a[i], a[i], sq[i]);
        }
#pragma unroll
        for (int j = 0; j < 16; j++) {
            float p = Ps[(tx + 16 * j) * 129 + d];
#pragma unroll
            for (int i = 0; i < 4; i++) acc[i][j] = fmaf(a[i], p, acc[i][j]);
        }
    }
    float rmax[4];
#pragma unroll
    for (int i = 0; i < 4; i++) {
        float hlf = 0.5f * sq[i];
        float mx = -1e30f;
#pragma unroll
        for (int j = 0; j < 16; j++) {
            acc[i][j] -= hlf;
            mx = fmaxf(mx, acc[i][j]);
        }
        rmax[i] = mx;
    }
    if (isq) {
#pragma unroll
        for (int o = 1; o < 16; o <<= 1)
#pragma unroll
            for (int i = 0; i < 4; i++)
                rmax[i] = fmaxf(rmax[i], __shfl_xor_sync(0xffffffffu, rmax[i], o));
#pragma unroll
        for (int i = 0; i < 4; i++) {
            size_t ro = (row0 + ty * 4 + i) * 256;
#pragma unroll
            for (int j = 0; j < 16; j++) {
                float v = expf(acc[i][j] - rmax[i]) * 0.0625f + 1e-6f;
                __nv_bfloat16 h, l;
                bsplit(v, h, l);
                outh[ro + tx + 16 * j] = h;
                outl[ro + tx + 16 * j] = l;
            }
        }
    } else {
#pragma unroll
        for (int i = 0; i < 4; i++) {
            size_t ro = (row0 + ty * 4 + i) * 256;
#pragma unroll
            for (int j = 0; j < 16; j++)
                outf[ro + tx + 16 * j] = acc[i][j];
        }
        __shared__ float red[256];
        float mx = fmaxf(fmaxf(rmax[0], rmax[1]), fmaxf(rmax[2], rmax[3]));
        red[t] = mx;
        __syncthreads();
        for (int o = 128; o > 0; o >>= 1) {
            if (t < o) red[t] = fmaxf(red[t], red[t + o]);
            __syncthreads();
        }
        if (t == 0) partials[blockIdx.x] = red[0];
    }
}

__global__ void reduce_max_kernel(const float* __restrict__ partials, int n)
{
    __shared__ float red[256];
    int t = threadIdx.x;
    float mx = -1e30f;
    for (int i = t; i < n; i += 256) mx = fmaxf(mx, partials[i]);
    red[t] = mx; __syncthreads();
    for (int o = 128; o > 0; o >>= 1) {
        if (t < o) red[t] = fmaxf(red[t], red[t + o]);
        __syncthreads();
    }
    if (t == 0) g_zmax = red[0];
}

// phi_k: fp32 in place + bf16 hi/lo
__global__ void expk_kernel(float* __restrict__ Z, __nv_bfloat16* __restrict__ oh,
                            __nv_bfloat16* __restrict__ ol, size_t n)
{
    size_t i = (size_t)blockIdx.x * blockDim.x + threadIdx.x;
    if (i < n) {
        float v = expf(Z[i] - g_zmax) * 0.0625f + 1e-6f;
        Z[i] = v;
        __nv_bfloat16 h, l;
        bsplit(v, h, l);
        oh[i] = h; ol[i] = l;
    }
}

// ---------------- v transpose-split: [bh,s,d] -> [bh,d,s] hi/lo ---------------
__global__ void vt_split_kernel()
{
    __shared__ float tile[32][33];
    int d0 = blockIdx.x * 32, s0 = blockIdx.y * 32, bh = blockIdx.z;
    int tx = threadIdx.x & 31, ty = threadIdx.x >> 5;
    const float* src = g_v + (size_t)bh * Ss * 128;
#pragma unroll
    for (int yy = 0; yy < 4; yy++)
        tile[ty + yy * 8][tx] = src[(size_t)(s0 + ty + yy * 8) * 128 + d0 + tx];
    __syncthreads();
#pragma unroll
    for (int yy = 0; yy < 4; yy++) {
        int d = d0 + ty + yy * 8;
        float v = tile[tx][ty + yy * 8];
        __nv_bfloat16 h, l; bsplit(v, h, l);
        size_t o = ((size_t)bh * 128 + d) * 4096 + s0 + tx;
        g_vth[o] = h; g_vtl[o] = l;
    }
}

// ---------------- kv transpose-split: [bhc,m,d] -> [bhc,d,m] hi/lo ------------
__global__ void kvt_split_kernel()
{
    __shared__ float tile[32][33];
    int d0 = blockIdx.x * 32, m0 = blockIdx.y * 32;
    size_t bhc = blockIdx.z;
    int tx = threadIdx.x & 31, ty = threadIdx.x >> 5;
    const float* src = g_kv + bhc * 32768;
#pragma unroll
    for (int yy = 0; yy < 4; yy++)
        tile[ty + yy * 8][tx] = src[(size_t)(m0 + ty + yy * 8) * 128 + d0 + tx];
    __syncthreads();
#pragma unroll
    for (int yy = 0; yy < 4; yy++) {
        int d = d0 + ty + yy * 8;
        float v = tile[tx][ty + yy * 8];
        __nv_bfloat16 h, l; bsplit(v, h, l);
        size_t o = bhc * 32768 + (size_t)d * 256 + m0 + tx;
        g_kvth[o] = h; g_kvtl[o] = l;
    }
}

// ---------------- per-chunk KV = phi_k^T @ v (fp32) ---------------------------
__global__ void kvchunk_kernel()
{
    __shared__ float pks[32 * 256];
    __shared__ float vs[32 * 64];
    int dh = blockIdx.x;
    int c  = blockIdx.y;
    int bh = blockIdx.z;
    int t = threadIdx.x, tx = t & 15, ty = t >> 4;
    const float* pk = g_phik + ((size_t)bh * Ss + (size_t)c * 128) * 256;
    const float* vv = g_v    + ((size_t)bh * Ss + (size_t)c * 128) * 128 + dh * 64;
    float acc[16][4];
#pragma unroll
    for (int a = 0; a < 16; a++)
#pragma unroll
        for (int b2 = 0; b2 < 4; b2++) acc[a][b2] = 0.f;

    for (int j0 = 0; j0 < 128; j0 += 32) {
        __syncthreads();
        for (int i = t; i < 32 * 256; i += 256) pks[i] = pk[(size_t)j0 * 256 + i];
        for (int i = t; i < 32 * 64; i += 256) {
            int j = i >> 6, d = i & 63;
            vs[i] = vv[(size_t)(j0 + j) * 128 + d];
        }
        __syncthreads();
        for (int j = 0; j < 32; j++) {
            float a[16], b4[4];
#pragma unroll
            for (int mi = 0; mi < 16; mi++) a[mi] = pks[j * 256 + tx + 16 * mi];
#pragma unroll
            for (int di = 0; di < 4; di++) b4[di] = vs[j * 64 + ty * 4 + di];
#pragma unroll
            for (int mi = 0; mi < 16; mi++)
#pragma unroll
                for (int di = 0; di < 4; di++)
                    acc[mi][di] = fmaf(a[mi], b4[di], acc[mi][di]);
        }
    }
    float* outp = g_kv + (((size_t)bh * NCn + c) * 256) * 128 + dh * 64;
#pragma unroll
    for (int mi = 0; mi < 16; mi++)
#pragma unroll
        for (int di = 0; di < 4; di++)
            outp[(size_t)(tx + 16 * mi) * 128 + ty * 4 + di] = acc[mi][di];
}

__global__ void kvprefix_kernel()
{
    int e = blockIdx.x * 256 + threadIdx.x;
    int bh = blockIdx.y;
    size_t base = (size_t)bh * NCn * 32768 + e;
    float run = 0.f;
    for (int c = 0; c < NCn; c++) {
        size_t p = base + (size_t)c * 32768;
        float v = g_kv[p];
        g_kv[p] = run;
        run += v;
    }
}

__global__ void ksum_kernel()
{
    int c = blockIdx.x, bh = blockIdx.y, m = threadIdx.x;
    const float* pk = g_phik + ((size_t)bh * Ss + (size_t)c * 128) * 256;
    float s = 0.f;
    for (int j = 0; j < 128; j++) s += pk[(size_t)j * 256 + m];
    g_ksum[((size_t)bh * NCn + c) * 256 + m] = s;
}

__global__ void ksumprefix_kernel()
{
    int bh = blockIdx.x, m = threadIdx.x;
    float run = 0.f;
    for (int c = 0; c < NCn; c++) {
        size_t p = ((size_t)bh * NCn + c) * 256 + m;
        float v = g_ksum[p];
        g_ksum[p] = run;
        run += v;
    }
}

// ---------------- attention main (HMMA) ---------------------------------------
// smem map (bytes): stages [0, 147456) two x 73728; P_hi @147456 (34816);
// P_lo @182272; den_part @217088 (2048); den2 @219136 (512); den_s @219648 (512);
// ksum @220160 (1024). total 221184.
#define ATTN_SMEM 221184
__global__ void __launch_bounds__(256, 1) attn_kernel()
{
    extern __shared__ char smem[];
    const uint32_t sb = smem_u32(smem);
    const int t = threadIdx.x, lane = t & 31, wid = t >> 5;
    const int wm = wid >> 2, wn = wid & 3;
    const int c = blockIdx.x, h = blockIdx.y, b = blockIdx.z;
    const int kvh = h >> 1, bh = b * HKVn + kvh;
    const size_t qoff = (((size_t)(b * Hh + h)) * Ss + (size_t)c * 128) * 256;
    const size_t koff = ((size_t)bh * Ss + (size_t)c * 128) * 256;

    float* den_part = (float*)(smem + 217088);
    float* den2_arr = (float*)(smem + 219136);
    float* den_s    = (float*)(smem + 219648);
    float* ksum_s   = (float*)(smem + 220160);

    ksum_s[t] = g_ksum[((size_t)bh * NCn + c) * 256 + t];

    const int arow = wm * 64 + (lane & 15);
    const int acolB = (lane >> 4) * 16;
    const int brow = wn * 32 + (lane & 7) + ((lane >> 4) & 1) * 8;
    const int bcolB = ((lane >> 3) & 1) * 16;

    // ---- phase A: P = phi_q @ phi_k^T (k = 256, chunks of 64) ----
    const __nv_bfloat16* srcsA[4] = { g_phiqh + qoff, g_phiql + qoff,
                                      g_phikh + koff, g_phikl + koff };
    auto issueA = [&](int s, int kc) {
        uint32_t base = sb + s * 73728;
#pragma unroll
        for (int idx = t; idx < 4096; idx += 256) {
            int tile = idx >> 10, rem = idx & 1023;
            int r = rem >> 3, v = rem & 7;
            cp16(base + tile * 18432 + r * 144 + v * 16,
                 srcsA[tile] + (size_t)r * 256 + kc * 64 + v * 8);
        }
        cp_commit();
    };

    float accP[4][4][4];
#pragma unroll
    for (int i = 0; i < 4; i++)
#pragma unroll
        for (int j = 0; j < 4; j++)
#pragma unroll
            for (int k = 0; k < 4; k++) accP[i][j][k] = 0.f;

    issueA(0, 0); issueA(1, 1);
    for (int kc = 0; kc < 4; kc++) {
        cp_wait1();
        __syncthreads();
        uint32_t bs = sb + (kc & 1) * 73728;
#pragma unroll
        for (int ks = 0; ks < 4; ks++) {
            int kb = ks * 32;
            uint32_t qh[4][4], ql[4][4], bhf[4][2], blf[4][2];
#pragma unroll
            for (int i = 0; i < 4; i++) {
                uint32_t off = (uint32_t)(arow + i * 16) * 144 + kb + acolB;
                ldmx4(qh[i], bs + off);
                ldmx4(ql[i], bs + 18432 + off);
            }
#pragma unroll
            for (int nt = 0; nt < 2; nt++) {
                uint32_t off = (uint32_t)(brow + nt * 16) * 144 + kb + bcolB;
                uint32_t rh[4], rl[4];
                ldmx4(rh, bs + 36864 + off);
                ldmx4(rl, bs + 55296 + off);
                bhf[nt * 2][0] = rh[0]; bhf[nt * 2][1] = rh[1];
                bhf[nt * 2 + 1][0] = rh[2]; bhf[nt * 2 + 1][1] = rh[3];
                blf[nt * 2][0] = rl[0]; blf[nt * 2][1] = rl[1];
                blf[nt * 2 + 1][0] = rl[2]; blf[nt * 2 + 1][1] = rl[3];
            }
#pragma unroll
            for (int i = 0; i < 4; i++)
#pragma unroll
                for (int j = 0; j < 4; j++) {
                    mma16816(accP[i][j], qh[i], bhf[j]);
                    mma16816(accP[i][j], qh[i], blf[j]);
                    mma16816(accP[i][j], ql[i], bhf[j]);
                }
        }
        __syncthreads();
        if (kc + 2 < 4) issueA(kc & 1, kc + 2);
        else cp_commit();
    }

    // ---- mask, split P to smem, row sums ----
    __nv_bfloat16* Ph = (__nv_bfloat16*)(smem + 147456);
    __nv_bfloat16* Pl = (__nv_bfloat16*)(smem + 182272);
#pragma unroll
    for (int i = 0; i < 4; i++) {
        int r1 = wm * 64 + i * 16 + (lane >> 2);
        float rs1 = 0.f, rs2 = 0.f;
#pragma unroll
        for (int j = 0; j < 4; j++) {
            int n0 = wn * 32 + j * 8 + (lane & 3) * 2;
            float m00 = (n0     <= r1    ) ? accP[i][j][0] : 0.f;
            float m01 = (n0 + 1 <= r1    ) ? accP[i][j][1] : 0.f;
            float m10 = (n0     <= r1 + 8) ? accP[i][j][2] : 0.f;
            float m11 = (n0 + 1 <= r1 + 8) ? accP[i][j][3] : 0.f;
            rs1 += m00 + m01; rs2 += m10 + m11;
            __nv_bfloat16 hh, llv;
            bsplit(m00, hh, llv); Ph[r1 * 136 + n0] = hh;       Pl[r1 * 136 + n0] = llv;
            bsplit(m01, hh, llv); Ph[r1 * 136 + n0 + 1] = hh;   Pl[r1 * 136 + n0 + 1] = llv;
            bsplit(m10, hh, llv); Ph[(r1 + 8) * 136 + n0] = hh; Pl[(r1 + 8) * 136 + n0] = llv;
            bsplit(m11, hh, llv); Ph[(r1 + 8) * 136 + n0 + 1] = hh; Pl[(r1 + 8) * 136 + n0 + 1] = llv;
        }
        rs1 += __shfl_xor_sync(0xffffffffu, rs1, 1);
        rs1 += __shfl_xor_sync(0xffffffffu, rs1, 2);
        rs2 += __shfl_xor_sync(0xffffffffu, rs2, 1);
        rs2 += __shfl_xor_sync(0xffffffffu, rs2, 2);
        if ((lane & 3) == 0) {
            den_part[wn * 128 + r1] = rs1;
            den_part[wn * 128 + r1 + 8] = rs2;
        }
    }
    __syncthreads();
    if (t < 128)
        den_s[t] = den_part[t] + den_part[128 + t] + den_part[256 + t] + den_part[384 + t];

    // ---- phase B: O = P @ v  (v_t[d, s] in smem, k = 128) ----
    const __nv_bfloat16* vtsrc[2] = {
        g_vth + (size_t)bh * 128 * 4096 + c * 128,
        g_vtl + (size_t)bh * 128 * 4096 + c * 128 };
#pragma unroll
    for (int idx = t; idx < 4096; idx += 256) {
        int tile = idx >> 11, rem = idx & 2047;
        int r = rem >> 4, v = rem & 15;
        cp16(sb + tile * 34816 + r * 272 + v * 16, vtsrc[tile] + (size_t)r * 4096 + v * 8);
    }
    cp_commit();
    cp_wait0();
    __syncthreads();

    float accO[4][4][4];
#pragma unroll
    for (int i = 0; i < 4; i++)
#pragma unroll
        for (int j = 0; j < 4; j++)
#pragma unroll
            for (int k = 0; k < 4; k++) accO[i][j][k] = 0.f;

#pragma unroll
    for (int ks = 0; ks < 8; ks++) {
        int kb = ks * 32;
        uint32_t ah_[4][4], al_[4][4], bhf[4][2], blf[4][2];
#pragma unroll
        for (int i = 0; i < 4; i++) {
            uint32_t off = (uint32_t)(arow + i * 16) * 272 + kb + acolB;
            ldmx4(ah_[i], sb + 147456 + off);
            ldmx4(al_[i], sb + 182272 + off);
        }
#pragma unroll
        for (int nt = 0; nt < 2; nt++) {
            uint32_t off = (uint32_t)(brow + nt * 16) * 272 + kb + bcolB;
            uint32_t rh[4], rl[4];
            ldmx4(rh, sb + off);
            ldmx4(rl, sb + 34816 + off);
            bhf[nt * 2][0] = rh[0]; bhf[nt * 2][1] = rh[1];
            bhf[nt * 2 + 1][0] = rh[2]; bhf[nt * 2 + 1][1] = rh[3];
            blf[nt * 2][0] = rl[0]; blf[nt * 2][1] = rl[1];
            blf[nt * 2 + 1][0] = rl[2]; blf[nt * 2 + 1][1] = rl[3];
        }
#pragma unroll
        for (int i = 0; i < 4; i++)
#pragma unroll
            for (int j = 0; j < 4; j++) {
                mma16816(accO[i][j], ah_[i], bhf[j]);
                mma16816(accO[i][j], ah_[i], blf[j]);
                mma16816(accO[i][j], al_[i], bhf[j]);
            }
    }
    __syncthreads();

    // ---- phase C: O += phi_q @ KV_pre (kv_t[d, m], k = 256, chunks 64) ----
    const __nv_bfloat16* srcsC[4] = { g_phiqh + qoff, g_phiql + qoff,
        g_kvth + ((size_t)bh * NCn + c) * 32768,
        g_kvtl + ((size_t)bh * NCn + c) * 32768 };
    auto issueC = [&](int s, int kc) {
        uint32_t base = sb + s * 73728;
#pragma unroll
        for (int idx = t; idx < 4096; idx += 256) {
            int tile = idx >> 10, rem = idx & 1023;
            int r = rem >> 3, v = rem & 7;
            cp16(base + tile * 18432 + r * 144 + v * 16,
                 srcsC[tile] + (size_t)r * 256 + kc * 64 + v * 8);
        }
        cp_commit();
    };

    float den2r = 0.f;
    issueC(0, 0); issueC(1, 1);
    for (int kc = 0; kc < 4; kc++) {
        cp_wait1();
        __syncthreads();
        uint32_t bs = sb + (kc & 1) * 73728;
#pragma unroll
        for (int ks = 0; ks < 4; ks++) {
            int kb = ks * 32;
            uint32_t qh[4][4], ql[4][4], bhf[4][2], blf[4][2];
#pragma unroll
            for (int i = 0; i < 4; i++) {
                uint32_t off = (uint32_t)(arow + i * 16) * 144 + kb + acolB;
                ldmx4(qh[i], bs + off);
                ldmx4(ql[i], bs + 18432 + off);
            }
#pragma unroll
            for (int nt = 0; nt < 2; nt++) {
                uint32_t off = (uint32_t)(brow + nt * 16) * 144 + kb + bcolB;
                uint32_t rh[4], rl[4];
                ldmx4(rh, bs + 36864 + off);
                ldmx4(rl, bs + 55296 + off);
                bhf[nt * 2][0] = rh[0]; bhf[nt * 2][1] = rh[1];
                bhf[nt * 2 + 1][0] = rh[2]; bhf[nt * 2 + 1][1] = rh[3];
                blf[nt * 2][0] = rl[0]; blf[nt * 2][1] = rl[1];
                blf[nt * 2 + 1][0] = rl[2]; blf[nt * 2 + 1][1] = rl[3];
            }
#pragma unroll
            for (int i = 0; i < 4; i++)
#pragma unroll
                for (int j = 0; j < 4; j++) {
                    mma16816(accO[i][j], qh[i], bhf[j]);
                    mma16816(accO[i][j], qh[i], blf[j]);
                    mma16816(accO[i][j], ql[i], bhf[j]);
                }
        }
        if (t < 128) {
            const __nv_bfloat16* qh_e = (const __nv_bfloat16*)(smem + (kc & 1) * 73728);
            const __nv_bfloat16* ql_e = qh_e + 9216;
            for (int mm = 0; mm < 64; mm++)
                den2r += (__bfloat162float(qh_e[t * 72 + mm]) +
                          __bfloat162float(ql_e[t * 72 + mm])) * ksum_s[kc * 64 + mm];
        }
        __syncthreads();
        if (kc + 2 < 4) issueC(kc & 1, kc + 2);
        else cp_commit();
    }
    if (t < 128) den2_arr[t] = den2r;
    __syncthreads();

    // ---- epilogue: divide by den, store ----
#pragma unroll
    for (int i = 0; i < 4; i++) {
        int r1 = wm * 64 + i * 16 + (lane >> 2);
        float dn1 = den_s[r1] + den2_arr[r1] + 1e-6f;
        float dn2 = den_s[r1 + 8] + den2_arr[r1 + 8] + 1e-6f;
        int s1 = c * 128 + r1;
#pragma unroll
        for (int j = 0; j < 4; j++) {
            int n0 = wn * 32 + j * 8 + (lane & 3) * 2;
            float2 v1 = { accO[i][j][0] / dn1, accO[i][j][1] / dn1 };
            float2 v2 = { accO[i][j][2] / dn2, accO[i][j][3] / dn2 };
            *(float2*)(g_attn + ((size_t)b * Ss + s1) * 2048 + h * 128 + n0) = v1;
            *(float2*)(g_attn + ((size_t)b * Ss + s1 + 8) * 2048 + h * 128 + n0) = v2;
        }
    }
}

// ---------------- launch ------------------------------------------------------
extern "C" void kernel_launch(void* const* d_in, const int* in_sizes, int n_in,
                              void* d_out, int out_size)
{
    const float* hs   = (const float*)d_in[0];
    const float* cosp = (const float*)d_in[1];
    const float* sinp = (const float*)d_in[2];
    const float* wq   = (const float*)d_in[3];
    const float* wk   = (const float*)d_in[4];
    const float* wv   = (const float*)d_in[5];
    const float* wo   = (const float*)d_in[6];
    const float* proj = (const float*)d_in[7];
    float* out = (float*)d_out;

    float *pq_, *pk_, *pv_, *pphik, *ppart, *pattn;
    cudaGetSymbolAddress((void**)&pq_,   g_q);
    cudaGetSymbolAddress((void**)&pk_,   g_k);
    cudaGetSymbolAddress((void**)&pv_,   g_v);
    cudaGetSymbolAddress((void**)&pphik, g_phik);
    cudaGetSymbolAddress((void**)&ppart, g_part);
    cudaGetSymbolAddress((void**)&pattn, g_attn);
    __nv_bfloat16 *ah, *al, *wqh, *wql, *wkh, *wkl, *wvh, *wvl, *woh, *wol;
    __nv_bfloat16 *phiqh, *phiql, *phikh, *phikl;
    cudaGetSymbolAddress((void**)&ah,  g_ah);
    cudaGetSymbolAddress((void**)&al,  g_al);
    cudaGetSymbolAddress((void**)&wqh, g_wqh);
    cudaGetSymbolAddress((void**)&wql, g_wql);
    cudaGetSymbolAddress((void**)&wkh, g_wkh);
    cudaGetSymbolAddress((void**)&wkl, g_wkl);
    cudaGetSymbolAddress((void**)&wvh, g_wvh);
    cudaGetSymbolAddress((void**)&wvl, g_wvl);
    cudaGetSymbolAddress((void**)&woh, g_woh);
    cudaGetSymbolAddress((void**)&wol, g_wol);
    cudaGetSymbolAddress((void**)&phiqh, g_phiqh);
    cudaGetSymbolAddress((void**)&phiql, g_phiql);
    cudaGetSymbolAddress((void**)&phikh, g_phikh);
    cudaGetSymbolAddress((void**)&phikl, g_phikl);

    cudaFuncSetAttribute(featmap_kernel, cudaFuncAttributeMaxDynamicSharedMemorySize, 165120);
    cudaFuncSetAttribute(attn_kernel,    cudaFuncAttributeMaxDynamicSharedMemorySize, ATTN_SMEM);
    cudaFuncSetAttribute(hmma_gemm,      cudaFuncAttributeMaxDynamicSharedMemorySize, 2 * STG_BYTES);

    // splits
    split_kernel<<<16384, 256>>>(hs, ah, al, 4194304);
    split_kernel<<<4096,  256>>>(wq, wqh, wql, 1048576);
    split_kernel<<<2048,  256>>>(wk, wkh, wkl, 524288);
    split_kernel<<<2048,  256>>>(wv, wvh, wvl, 524288);
    split_kernel<<<4096,  256>>>(wo, woh, wol, 1048576);

    // QKV projections
    hmma_gemm<<<dim3(16, 64), 256, 2 * STG_BYTES>>>(ah, al, wqh, wql, pq_, 2048, 1, 16);
    hmma_gemm<<<dim3(8,  64), 256, 2 * STG_BYTES>>>(ah, al, wkh, wkl, pk_, 1024, 1, 8);
    hmma_gemm<<<dim3(8,  64), 256, 2 * STG_BYTES>>>(ah, al, wvh, wvl, pv_, 1024, 1, 8);

    // RoPE
    rope_kernel<<<(Bb * Hh * Ss * 64) / 256, 256>>>(pq_, cosp, sinp, Hh);
    rope_kernel<<<(Bb * HKVn * Ss * 64) / 256, 256>>>(pk_, cosp, sinp, HKVn);

    // feature maps
    featmap_kernel<<<(Bb * Hh * Ss) / 64, 256, 165120>>>(pq_, proj, nullptr, phiqh, phiql, ppart, 1);
    featmap_kernel<<<(Bb * HKVn * Ss) / 64, 256, 165120>>>(pk_, proj, pphik, nullptr, nullptr, ppart, 0);
    reduce_max_kernel<<<1, 256>>>(ppart, (Bb * HKVn * Ss) / 64);
    expk_kernel<<<(Bb * HKVn * Ss * Mm) / 256, 256>>>(pphik, phikh, phikl, (size_t)Bb * HKVn * Ss * Mm);

    // v transpose-split
    vt_split_kernel<<<dim3(4, 128, Bb * HKVn), 256>>>();

    // chunk states
    kvchunk_kernel<<<dim3(2, NCn, Bb * HKVn), 256>>>();
    kvprefix_kernel<<<dim3(128, Bb * HKVn), 256>>>();
    ksum_kernel<<<dim3(NCn, Bb * HKVn), 256>>>();
    ksumprefix_kernel<<<Bb * HKVn, 256>>>();
    kvt_split_kernel<<<dim3(4, 8, Bb * HKVn * NCn), 256>>>();

    // attention (HMMA)
    attn_kernel<<<dim3(NCn, Hh, Bb), 256, ATTN_SMEM>>>();

    // output projection
    split_kernel<<<16384, 256>>>(pattn, ah, al, 4194304);
    hmma_gemm<<<dim3(16, 64), 256, 2 * STG_BYTES>>>(ah, al, woh, wol, out, 2048, 0, 0);
}